// round 12
// baseline (speedup 1.0000x reference)
#include <cuda_runtime.h>
#include <cstdint>

#define TSEQ 512
#define BT   32
#define NCTA 64
#define NTHR 256

// dynamic smem layout (u32 word indices)
#define S_WIH0 0      // 4096 words: resident Wih0 bf16 A-frags [w][mt][L][4]
#define S_H0F  4096   // 2048 words: h0 bf16 B-frags
#define S_H1F  6144   // 2048 words: h1 bf16 B-frags
#define S_XF   8192   // 2 x 256 words: x bf16 B-frags (double buffered)
#define S_C0   8704   // 4096 words: fp32 c-state layer 0 [16][NTHR]
#define S_C1   12800  // 4096 words: fp32 c-state layer 1
#define SMEM_WORDS 16896
#define SMEM_BYTES (SMEM_WORDS*4)

// persistent device scratch
__device__ uint32_t g_WF[24*8*4*32*4];            // bf16 frag-major weights, q-major
__device__ uint32_t g_xB[(size_t)NCTA*TSEQ*256];  // bf16 x B-frags
__device__ float g_b[2][512];                     // fused biases

__device__ __forceinline__ uint32_t bf2(float a, float b){
    uint32_t r;
    asm("{.reg .b16 lo, hi;\n\tcvt.rn.bf16.f32 lo, %1;\n\tcvt.rn.bf16.f32 hi, %2;\n\t"
        "mov.b32 %0, {lo, hi};}" : "=r"(r) : "f"(a), "f"(b));
    return r;
}
__device__ __forceinline__ uint16_t bfr(float v){
    uint16_t r; asm("cvt.rn.bf16.f32 %0, %1;" : "=h"(r) : "f"(v)); return r;
}

// ---------------- setup: bf16 frag-major packing ---------------------------
// q: 0-7 = Whh0 (seg0), 8-15 = Wih1 (seg1), 16-23 = Whh1 (seg2)
__global__ void setup_kernel(const float* __restrict__ x,
    const float* __restrict__ Whh0, const float* __restrict__ Wih1,
    const float* __restrict__ Whh1,
    const float* __restrict__ bih0, const float* __restrict__ bhh0,
    const float* __restrict__ bih1, const float* __restrict__ bhh1)
{
    long long idx0 = blockIdx.x*(long long)blockDim.x + threadIdx.x;
    long long stride = (long long)gridDim.x*blockDim.x;

    for (long long idx = idx0; idx < 98304; idx += stride){
        int i  = (int)(idx & 3);
        int L  = (int)((idx >> 2) & 31);
        int mt = (int)((idx >> 7) & 3);
        int w  = (int)((idx >> 9) & 7);
        int q  = (int)(idx >> 12);
        int m  = q >> 3, kt = q & 7;
        int gid = L >> 2, tig = L & 3;
        int row = mt*128 + 16*w + gid + (i&1)*8;
        int col = kt*16 + 2*tig + (i>>1)*8;
        const float* W = (m==0) ? Whh0 : (m==1) ? Wih1 : Whh1;
        g_WF[idx] = bf2(W[row*128 + col], W[row*128 + col + 1]);
    }
    for (long long idx = idx0; idx < (long long)NCTA*TSEQ*256; idx += stride){
        int cta = (int)(idx >> 17);
        int rem = (int)(idx & 131071);
        int t   = rem >> 8;
        int e   = rem & 255;
        int reg = e & 1, L = (e>>1)&31, nt = e>>6;
        int gid = L>>2, tig = L&3;
        int b = cta*32 + nt*8 + gid;
        int k0 = 2*tig + reg*8;
        float v0 = (k0   < 14) ? x[((size_t)b*TSEQ + t)*14 + k0    ] : 0.f;
        float v1 = (k0+1 < 14) ? x[((size_t)b*TSEQ + t)*14 + k0 + 1] : 0.f;
        g_xB[idx] = bf2(v0, v1);
    }
    for (long long n = idx0; n < 512; n += stride){
        g_b[0][n] = bih0[n] + bhh0[n];
        g_b[1][n] = bih1[n] + bhh1[n];
    }
}

// ---------------- device helpers -------------------------------------------
__device__ __forceinline__ void mma16(float* d, uint4 a, uint2 b){
    asm volatile("mma.sync.aligned.m16n8k16.row.col.f32.bf16.bf16.f32 "
        "{%0,%1,%2,%3}, {%4,%5,%6,%7}, {%8,%9}, {%0,%1,%2,%3};"
        : "+f"(d[0]), "+f"(d[1]), "+f"(d[2]), "+f"(d[3])
        : "r"(a.x), "r"(a.y), "r"(a.z), "r"(a.w), "r"(b.x), "r"(b.y));
}
__device__ __forceinline__ uint4 ldgA(int q, int w, int mt, int L){
    const uint4* p = (const uint4*)g_WF;
    return __ldg(p + (((q*8 + w)*4 + mt)*32 + L));
}
__device__ __forceinline__ float tanhapx(float x){
    float r; asm("tanh.approx.f32 %0, %1;" : "=f"(r) : "f"(x)); return r;
}
__device__ __forceinline__ float sigapx(float x){
    return fmaf(tanhapx(0.5f*x), 0.5f, 0.5f);
}
__device__ __forceinline__ void cp_x(uint32_t* dst, const uint32_t* src, int tid){
    unsigned d = (unsigned)__cvta_generic_to_shared(dst + tid);
    asm volatile("cp.async.ca.shared.global [%0], [%1], 4;" :: "r"(d), "l"(src + tid));
}
__device__ __forceinline__ void cp_commit(){ asm volatile("cp.async.commit_group;"); }
__device__ __forceinline__ void cp_wait0(){ asm volatile("cp.async.wait_group 0;"); }
__device__ __forceinline__ void cp_wait1(){ asm volatile("cp.async.wait_group 1;"); }

// biases via L1-resident LDG (keeps them out of the register file)
__device__ __forceinline__ void initacc(float (&acc)[4][4][4], int layer, int w, int L){
    const int u_lo = 16*w + (L>>2), u_hi = u_lo + 8;
    #pragma unroll
    for (int g = 0; g < 4; g++){
        float blo = __ldg(&g_b[layer][g*128 + u_lo]);
        float bhi = __ldg(&g_b[layer][g*128 + u_hi]);
        #pragma unroll
        for (int nt = 0; nt < 4; nt++){
            acc[g][nt][0] = blo; acc[g][nt][1] = blo;
            acc[g][nt][2] = bhi; acc[g][nt][3] = bhi;
        }
    }
}

// one epilogue chunk: 2 cells of the LSTM cell update (hh = kt>>2, nt = kt&3)
__device__ __forceinline__ void epi_chunk(float (&acc)[4][4][4], float* csm,
                                          uint16_t* hs, int w, int L, int tid,
                                          int hh, int nt)
{
    const int gid = L >> 2, tig = L & 3;
    #pragma unroll
    for (int j = 0; j < 2; j++){
        int d = hh*2 + j;
        float i_ = sigapx(acc[0][nt][d]);
        float f_ = sigapx(acc[1][nt][d]);
        float g_ = tanhapx(acc[2][nt][d]);
        float o_ = sigapx(acc[3][nt][d]);
        int ci = hh*8 + nt*2 + j;
        float cc = f_*csm[ci*NTHR + tid] + i_*g_;
        csm[ci*NTHR + tid] = cc;
        float h = o_*tanhapx(cc);
        int Lp = (2*tig + j)*4 + (gid >> 1);
        int off16 = ((w*4 + nt)*32 + Lp)*4 + hh*2 + (gid & 1);
        hs[off16] = bfr(h);
    }
}

// exec-position -> q map: p<8 -> 16+p (seg2) ; 8<=p<16 -> p (seg1) ; else p-16 (seg0)
__device__ __forceinline__ constexpr int qof(int p){
    return (p < 8) ? 16 + p : (p < 16 ? p : p - 16);
}

// GEMM segment with interleaved epilogue consumption of the other acc
template<int POS0>
__device__ __forceinline__ void gemm_seg_epi(float (&accT)[4][4][4], uint4 (&A)[4][4],
    const uint32_t* __restrict__ hF, int w, int L,
    float (&accE)[4][4][4], float* csm, uint16_t* hs, int tid)
{
    uint2 B[2][4];
    #pragma unroll
    for (int nt = 0; nt < 4; nt++) B[0][nt] = *(const uint2*)(hF + (nt*32 + L)*2);
    #pragma unroll
    for (int kt = 0; kt < 8; kt++){
        const int p = POS0 + kt;
        const int qn = qof((p + 4) % 24);
        if (kt < 7){
            #pragma unroll
            for (int nt = 0; nt < 4; nt++)
                B[(kt+1)&1][nt] = *(const uint2*)(hF + (((kt+1)*4 + nt)*32 + L)*2);
        }
        #pragma unroll
        for (int mt = 0; mt < 4; mt++)
            #pragma unroll
            for (int nt = 0; nt < 4; nt++)
                mma16(accT[mt][nt], A[p&3][mt], B[kt&1][nt]);
        #pragma unroll
        for (int mt = 0; mt < 4; mt++)
            A[p&3][mt] = ldgA(qn, w, mt, L);
        epi_chunk(accE, csm, hs, w, L, tid, kt>>2, kt&3);
    }
}

// plain GEMM segment (seg1, positions 8..15)
__device__ __forceinline__ void gemm_seg1(float (&acc)[4][4][4], uint4 (&A)[4][4],
                                          const uint32_t* __restrict__ hF, int w, int L)
{
    uint2 B[2][4];
    #pragma unroll
    for (int nt = 0; nt < 4; nt++) B[0][nt] = *(const uint2*)(hF + (nt*32 + L)*2);
    #pragma unroll
    for (int kt = 0; kt < 8; kt++){
        const int p = 8 + kt;
        const int qn = qof((p + 4) % 24);
        if (kt < 7){
            #pragma unroll
            for (int nt = 0; nt < 4; nt++)
                B[(kt+1)&1][nt] = *(const uint2*)(hF + (((kt+1)*4 + nt)*32 + L)*2);
        }
        #pragma unroll
        for (int mt = 0; mt < 4; mt++)
            #pragma unroll
            for (int nt = 0; nt < 4; nt++)
                mma16(acc[mt][nt], A[p&3][mt], B[kt&1][nt]);
        #pragma unroll
        for (int mt = 0; mt < 4; mt++)
            A[p&3][mt] = ldgA(qn, w, mt, L);
    }
}

// x projection: A = resident Wih0 frags (smem), single K=16 tile
__device__ __forceinline__ void gemm_x(float (&acc)[4][4][4], const uint32_t* smW,
                                       const uint32_t* xf, int w, int L)
{
    uint4 a[4]; uint2 b[4];
    #pragma unroll
    for (int mt = 0; mt < 4; mt++)
        a[mt] = *(const uint4*)(smW + ((w*4 + mt)*32 + L)*4);
    #pragma unroll
    for (int nt = 0; nt < 4; nt++)
        b[nt] = *(const uint2*)(xf + (nt*32 + L)*2);
    #pragma unroll
    for (int mt = 0; mt < 4; mt++)
        #pragma unroll
        for (int nt = 0; nt < 4; nt++)
            mma16(acc[mt][nt], a[mt], b[nt]);
}

// ---------------- main persistent kernel ------------------------------------
__global__ void __launch_bounds__(NTHR, 1)
lstm_mma_kernel(const float* __restrict__ Wih0, const float* __restrict__ Wfc,
                const float* __restrict__ bfc, float* __restrict__ out)
{
    extern __shared__ uint32_t sm[];
    const int tid = threadIdx.x, w = tid >> 5, L = tid & 31;
    float* c0sm = (float*)(sm + S_C0);
    float* c1sm = (float*)(sm + S_C1);
    uint16_t* h0hs = (uint16_t*)(sm + S_H0F);
    uint16_t* h1hs = (uint16_t*)(sm + S_H1F);

    // resident Wih0 bf16 A-frags, K padded 14->16
    for (int idx = tid; idx < 4096; idx += NTHR){
        int i = idx & 3, l = (idx>>2)&31, mt = (idx>>7)&3, ww = idx>>9;
        int gid = l>>2, tig = l&3;
        int row = mt*128 + 16*ww + gid + (i&1)*8;
        int c0i = 2*tig + (i>>1)*8;
        float v0 = (c0i   < 14) ? Wih0[row*14 + c0i    ] : 0.f;
        float v1 = (c0i+1 < 14) ? Wih0[row*14 + c0i + 1] : 0.f;
        sm[S_WIH0 + idx] = bf2(v0, v1);
    }
    for (int idx = tid; idx < 4096; idx += NTHR) sm[S_H0F + idx] = 0u;   // h0F+h1F
    for (int idx = tid; idx < 8192; idx += NTHR) sm[S_C0 + idx] = 0u;    // c0+c1

    const uint32_t* xsrc = g_xB + (size_t)blockIdx.x*TSEQ*256;
    cp_x(sm + S_XF,       xsrc,       tid); cp_commit();
    cp_x(sm + S_XF + 256, xsrc + 256, tid); cp_commit();
    cp_wait0();
    __syncthreads();

    float acc0[4][4][4], acc1[4][4][4];
    uint4 A[4][4];

    // prologue: acc0(t=0) = bias0 + x-proj(0)  (Whh0*h0=0 contributes nothing)
    initacc(acc0, 0, w, L);
    gemm_x(acc0, sm + S_WIH0, sm + S_XF, w, L);
    #pragma unroll
    for (int i = 0; i < 4; i++)
        #pragma unroll
        for (int mt = 0; mt < 4; mt++)
            A[i][mt] = ldgA(16 + i, w, mt, L);   // ring init: positions 0..3
    __syncthreads();   // protect x buf0 before t=0 refill; h/c zeros visible

    for (int t = 0; t < TSEQ; t++){
        // ---- phase B: seg2 = Whh1*h1(t-1) -> acc1  ||  epi0: acc0 -> h0(t)
        initacc(acc1, 1, w, L);
        gemm_seg_epi<0>(acc1, A, sm + S_H1F, w, L, acc0, c0sm, h0hs, tid);
        if (t + 2 < TSEQ){
            cp_x(sm + S_XF + (t&1)*256, xsrc + (size_t)(t+2)*256, tid);
            cp_commit();
            cp_wait1();
        } else {
            cp_wait0();
        }
        __syncthreads();   // h0(t) visible; h1(t-1) reads complete; x(t+1) visible

        // ---- phase A: seg1 = Wih1*h0(t) -> acc1; then
        //      [x-proj(t+1) + seg0 = Whh0*h0(t)] -> acc0  ||  epi1: acc1 -> h1(t)
        gemm_seg1(acc1, A, sm + S_H0F, w, L);
        if (t + 1 < TSEQ){
            initacc(acc0, 0, w, L);
            gemm_x(acc0, sm + S_WIH0, sm + S_XF + ((t+1)&1)*256, w, L);
            gemm_seg_epi<16>(acc0, A, sm + S_H0F, w, L, acc1, c1sm, h1hs, tid);
        } else {
            #pragma unroll
            for (int kt = 0; kt < 8; kt++)
                epi_chunk(acc1, c1sm, h1hs, w, L, tid, kt>>2, kt&3);
        }
        __syncthreads();   // h1(t) visible; h0(t) reads complete
    }

    // ---- FC + sigmoid on final h1 ----
    {
        float bias = bfc[0];
        #pragma unroll
        for (int bb = 0; bb < 4; bb++){
            int b = w*4 + bb;
            float s = 0.f;
            #pragma unroll
            for (int qq = 0; qq < 4; qq++){
                int u = L + 32*qq;
                int kt = u >> 4, k = u & 15;
                int reg = k >> 3, kk = k & 7;
                int Lp = (b & 7)*4 + (kk >> 1);
                int off16 = ((kt*4 + (b>>3))*32 + Lp)*4 + reg*2 + (kk & 1);
                float hv = __uint_as_float(((uint32_t)h1hs[off16]) << 16);
                s += hv * __ldg(Wfc + u);
            }
            #pragma unroll
            for (int off = 16; off; off >>= 1) s += __shfl_xor_sync(0xffffffffu, s, off);
            if (L == 0) out[blockIdx.x*BT + b] = sigapx(s + bias);
        }
    }
}

// ---------------- launch ----------------------------------------------------
extern "C" void kernel_launch(void* const* d_in, const int* in_sizes, int n_in,
                              void* d_out, int out_size)
{
    const float* x    = (const float*)d_in[0];
    const float* Wih0 = (const float*)d_in[1];
    const float* Whh0 = (const float*)d_in[2];
    const float* bih0 = (const float*)d_in[3];
    const float* bhh0 = (const float*)d_in[4];
    const float* Wih1 = (const float*)d_in[5];
    const float* Whh1 = (const float*)d_in[6];
    const float* bih1 = (const float*)d_in[7];
    const float* bhh1 = (const float*)d_in[8];
    const float* Wfc  = (const float*)d_in[9];
    const float* bfc  = (const float*)d_in[10];

    cudaFuncSetAttribute(lstm_mma_kernel,
                         cudaFuncAttributeMaxDynamicSharedMemorySize, SMEM_BYTES);

    setup_kernel<<<4096, 256>>>(x, Whh0, Wih1, Whh1, bih0, bhh0, bih1, bhh1);
    lstm_mma_kernel<<<NCTA, NTHR, SMEM_BYTES>>>(Wih0, Wfc, bfc, (float*)d_out);
}

// round 14
// speedup vs baseline: 1.4631x; 1.4631x over previous
#include <cuda_runtime.h>
#include <cstdint>

#define TSEQ 512
#define BT   16
#define NCTA 128
#define NTHR 256

// dynamic smem layout (u32 word indices)
#define S_WIH0 0      // 4096 words: resident Wih0 bf16 A-frags [w][mt][L][4]
#define S_H0F  4096   // 1024 words: h0 bf16 B-frags [8kt][2nt][32L][2]
#define S_H1F  5120   // 1024 words: h1 bf16 B-frags
#define S_XF   6144   // 2 x 128 words: x bf16 B-frags (double buffered)
#define SMEM_WORDS 6400
#define SMEM_BYTES (SMEM_WORDS*4)

// persistent device scratch
__device__ uint32_t g_WF[24*8*4*32*4];            // 393KB bf16 frag-major weights, q-major
__device__ uint32_t g_xB[(size_t)NCTA*TSEQ*128];  // 33MB bf16 x B-frags
__device__ float g_b[2][512];                     // fused biases

__device__ __forceinline__ uint32_t bf2(float a, float b){
    uint32_t r;
    asm("{.reg .b16 lo, hi;\n\tcvt.rn.bf16.f32 lo, %1;\n\tcvt.rn.bf16.f32 hi, %2;\n\t"
        "mov.b32 %0, {lo, hi};}" : "=r"(r) : "f"(a), "f"(b));
    return r;
}
__device__ __forceinline__ uint16_t bfr(float v){
    uint16_t r; asm("cvt.rn.bf16.f32 %0, %1;" : "=h"(r) : "f"(v)); return r;
}

// ---------------- setup: bf16 frag-major packing ---------------------------
// q = m*8 + kt; m: 0=Whh0(seg0), 1=Wih1(seg1), 2=Whh1(seg2)
__global__ void setup_kernel(const float* __restrict__ x,
    const float* __restrict__ Whh0, const float* __restrict__ Wih1,
    const float* __restrict__ Whh1,
    const float* __restrict__ bih0, const float* __restrict__ bhh0,
    const float* __restrict__ bih1, const float* __restrict__ bhh1)
{
    long long idx0 = blockIdx.x*(long long)blockDim.x + threadIdx.x;
    long long stride = (long long)gridDim.x*blockDim.x;

    // weights: g_WF[q][w][mt][L][i] (u32 = bf16x2)
    for (long long idx = idx0; idx < 98304; idx += stride){
        int i  = (int)(idx & 3);
        int L  = (int)((idx >> 2) & 31);
        int mt = (int)((idx >> 7) & 3);
        int w  = (int)((idx >> 9) & 7);
        int q  = (int)(idx >> 12);
        int m  = q >> 3, kt = q & 7;
        int gid = L >> 2, tig = L & 3;
        int row = mt*128 + 16*w + gid + (i&1)*8;
        int col = kt*16 + 2*tig + (i>>1)*8;
        const float* W = (m==0) ? Whh0 : (m==1) ? Wih1 : Whh1;
        g_WF[idx] = bf2(W[row*128 + col], W[row*128 + col + 1]);
    }
    // x B-frags: per (cta,t) 128 words, e = (nt*32+L)*2+reg, nt in {0,1}
    for (long long idx = idx0; idx < (long long)NCTA*TSEQ*128; idx += stride){
        int cta = (int)(idx >> 16);
        int rem = (int)(idx & 65535);
        int t   = rem >> 7;
        int e   = rem & 127;
        int reg = e & 1, L = (e>>1)&31, nt = e>>6;
        int gid = L>>2, tig = L&3;
        int b = cta*BT + nt*8 + gid;
        int k0 = 2*tig + reg*8;
        float v0 = (k0   < 14) ? x[((size_t)b*TSEQ + t)*14 + k0    ] : 0.f;
        float v1 = (k0+1 < 14) ? x[((size_t)b*TSEQ + t)*14 + k0 + 1] : 0.f;
        g_xB[idx] = bf2(v0, v1);
    }
    for (long long n = idx0; n < 512; n += stride){
        g_b[0][n] = bih0[n] + bhh0[n];
        g_b[1][n] = bih1[n] + bhh1[n];
    }
}

// ---------------- device helpers -------------------------------------------
__device__ __forceinline__ void mma16(float* d, uint4 a, uint2 b){
    asm volatile("mma.sync.aligned.m16n8k16.row.col.f32.bf16.bf16.f32 "
        "{%0,%1,%2,%3}, {%4,%5,%6,%7}, {%8,%9}, {%0,%1,%2,%3};"
        : "+f"(d[0]), "+f"(d[1]), "+f"(d[2]), "+f"(d[3])
        : "r"(a.x), "r"(a.y), "r"(a.z), "r"(a.w), "r"(b.x), "r"(b.y));
}
__device__ __forceinline__ uint4 ldgA(int q, int w, int mt, int L){
    const uint4* p = (const uint4*)g_WF;
    return __ldg(p + (((q*8 + w)*4 + mt)*32 + L));
}
__device__ __forceinline__ float tanhapx(float x){
    float r; asm("tanh.approx.f32 %0, %1;" : "=f"(r) : "f"(x)); return r;
}
__device__ __forceinline__ float sigapx(float x){
    return fmaf(tanhapx(0.5f*x), 0.5f, 0.5f);
}
__device__ __forceinline__ void cp_x(uint32_t* dst, const uint32_t* src, int tid){
    if (tid < 128){
        unsigned d = (unsigned)__cvta_generic_to_shared(dst + tid);
        asm volatile("cp.async.ca.shared.global [%0], [%1], 4;" :: "r"(d), "l"(src + tid));
    }
}
__device__ __forceinline__ void cp_commit(){ asm volatile("cp.async.commit_group;"); }
__device__ __forceinline__ void cp_wait0(){ asm volatile("cp.async.wait_group 0;"); }

__device__ __forceinline__ void initacc(float (&acc)[4][2][4], const float* bs){
    #pragma unroll
    for (int g = 0; g < 4; g++)
        #pragma unroll
        for (int nt = 0; nt < 2; nt++){
            acc[g][nt][0] = bs[g*2];   acc[g][nt][1] = bs[g*2];
            acc[g][nt][2] = bs[g*2+1]; acc[g][nt][3] = bs[g*2+1];
        }
}

// one 8-kt GEMM segment of the flat 24-q ring; A ring depth 4, refill q+4 mod 24
template<int SEG>
__device__ __forceinline__ void gemm_seg(float (&acc)[4][2][4], uint4 (&A)[4][4],
                                         const uint32_t* __restrict__ hF, int w, int L)
{
    uint2 B[2][2];
    #pragma unroll
    for (int nt = 0; nt < 2; nt++) B[0][nt] = *(const uint2*)(hF + (nt*32 + L)*2);
    #pragma unroll
    for (int kt = 0; kt < 8; kt++){
        const int q  = SEG*8 + kt;
        const int qn = (q + 4) % 24;
        if (kt < 7){
            #pragma unroll
            for (int nt = 0; nt < 2; nt++)
                B[(kt+1)&1][nt] = *(const uint2*)(hF + (((kt+1)*2 + nt)*32 + L)*2);
        }
        #pragma unroll
        for (int mt = 0; mt < 4; mt++)
            #pragma unroll
            for (int nt = 0; nt < 2; nt++)
                mma16(acc[mt][nt], A[q&3][mt], B[kt&1][nt]);
        #pragma unroll
        for (int mt = 0; mt < 4; mt++)
            A[q&3][mt] = ldgA(qn, w, mt, L);
    }
}

// x projection: A = resident Wih0 frags (smem), B = x frags, single K=16 tile
__device__ __forceinline__ void gemm_x(float (&acc)[4][2][4], const uint32_t* smW,
                                       const uint32_t* xf, int w, int L)
{
    uint4 a[4]; uint2 b[2];
    #pragma unroll
    for (int mt = 0; mt < 4; mt++)
        a[mt] = *(const uint4*)(smW + ((w*4 + mt)*32 + L)*4);
    #pragma unroll
    for (int nt = 0; nt < 2; nt++)
        b[nt] = *(const uint2*)(xf + (nt*32 + L)*2);
    #pragma unroll
    for (int mt = 0; mt < 4; mt++)
        #pragma unroll
        for (int nt = 0; nt < 2; nt++)
            mma16(acc[mt][nt], a[mt], b[nt]);
}

// LSTM cell epilogue: gates -> c,h; h scattered as bf16 into B-frag smem
__device__ __forceinline__ void epi(float (&acc)[4][2][4], float* cst,
                                    uint32_t* hF, int w, int L)
{
    uint16_t* hs = (uint16_t*)hF;
    const int gid = L >> 2, tig = L & 3;
    #pragma unroll
    for (int hh = 0; hh < 2; hh++)
        #pragma unroll
        for (int nt = 0; nt < 2; nt++)
            #pragma unroll
            for (int j = 0; j < 2; j++){
                int d = hh*2 + j;
                float i_ = sigapx(acc[0][nt][d]);
                float f_ = sigapx(acc[1][nt][d]);
                float g_ = tanhapx(acc[2][nt][d]);
                float o_ = sigapx(acc[3][nt][d]);
                int ci = hh*4 + nt*2 + j;
                float cc = f_*cst[ci] + i_*g_;
                cst[ci] = cc;
                float h = o_*tanhapx(cc);
                // u = 16w + gid + 8hh ; b = nt*8 + 2tig + j
                int Lp = (2*tig + j)*4 + (gid >> 1);
                int off16 = ((w*2 + nt)*32 + Lp)*4 + hh*2 + (gid & 1);
                hs[off16] = bfr(h);
            }
}

// ---------------- main persistent kernel ------------------------------------
__global__ void __launch_bounds__(NTHR, 1)
lstm_mma_kernel(const float* __restrict__ Wih0, const float* __restrict__ Wfc,
                const float* __restrict__ bfc, float* __restrict__ out)
{
    extern __shared__ uint32_t sm[];
    const int tid = threadIdx.x, w = tid >> 5, L = tid & 31;

    // resident Wih0 bf16 A-frags [w][mt][L][4], K padded 14->16
    for (int idx = tid; idx < 4096; idx += NTHR){
        int i = idx & 3, l = (idx>>2)&31, mt = (idx>>7)&3, ww = idx>>9;
        int gid = l>>2, tig = l&3;
        int row = mt*128 + 16*ww + gid + (i&1)*8;
        int c0 = 2*tig + (i>>1)*8;
        float v0 = (c0   < 14) ? Wih0[row*14 + c0    ] : 0.f;
        float v1 = (c0+1 < 14) ? Wih0[row*14 + c0 + 1] : 0.f;
        sm[S_WIH0 + idx] = bf2(v0, v1);
    }
    for (int idx = tid; idx < 2048; idx += NTHR) sm[S_H0F + idx] = 0u;   // h0F + h1F

    const int u_lo = 16*w + (L>>2), u_hi = u_lo + 8;
    float bs0[8], bs1[8];
    #pragma unroll
    for (int g = 0; g < 4; g++){
        bs0[g*2]   = g_b[0][g*128 + u_lo];
        bs0[g*2+1] = g_b[0][g*128 + u_hi];
        bs1[g*2]   = g_b[1][g*128 + u_lo];
        bs1[g*2+1] = g_b[1][g*128 + u_hi];
    }
    float c0[8], c1[8];
    #pragma unroll
    for (int i = 0; i < 8; i++){ c0[i] = 0.f; c1[i] = 0.f; }

    const uint32_t* xsrc = g_xB + (size_t)blockIdx.x*TSEQ*128;
    cp_x(sm + S_XF, xsrc, tid);
    cp_commit();
    cp_wait0();
    __syncthreads();

    float acc[4][2][4];
    uint4 A[4][4];
    #pragma unroll
    for (int q = 0; q < 4; q++)
        #pragma unroll
        for (int mt = 0; mt < 4; mt++)
            A[q][mt] = ldgA(q, w, mt, L);

    for (int t = 0; t < TSEQ; t++){
        // ---- layer 0: bias + x-proj + Whh0 * h0_old ----
        initacc(acc, bs0);
        gemm_x(acc, sm + S_WIH0, sm + S_XF + (t&1)*128, w, L);
        gemm_seg<0>(acc, A, sm + S_H0F, w, L);
        __syncthreads();                      // all reads of h0F_old done
        epi(acc, c0, sm + S_H0F, w, L);
        __syncthreads();                      // h0F_new visible

        // ---- layer 1: bias + Wih1 * h0_new + Whh1 * h1_old ----
        initacc(acc, bs1);
        if (t + 1 < TSEQ){
            cp_x(sm + S_XF + ((t+1)&1)*128, xsrc + (size_t)(t+1)*128, tid);
            cp_commit();
        }
        gemm_seg<1>(acc, A, sm + S_H0F, w, L);
        gemm_seg<2>(acc, A, sm + S_H1F, w, L);
        cp_wait0();
        __syncthreads();                      // all reads of h1F_old done
        epi(acc, c1, sm + S_H1F, w, L);
        __syncthreads();                      // h1F_new + x visible
    }

    // ---- FC + sigmoid on final h1 ----
    {
        const uint16_t* hs = (const uint16_t*)(sm + S_H1F);
        float bias = bfc[0];
        #pragma unroll
        for (int bb = 0; bb < 2; bb++){
            int b = w + 8*bb;
            float s = 0.f;
            #pragma unroll
            for (int qq = 0; qq < 4; qq++){
                int u = L + 32*qq;
                int kt = u >> 4, k = u & 15;
                int reg = k >> 3, kk = k & 7;
                int Lp = (b & 7)*4 + (kk >> 1);
                int off16 = ((kt*2 + (b>>3))*32 + Lp)*4 + reg*2 + (kk & 1);
                float hv = __uint_as_float(((uint32_t)hs[off16]) << 16);
                s += hv * __ldg(Wfc + u);
            }
            #pragma unroll
            for (int off = 16; off; off >>= 1) s += __shfl_xor_sync(0xffffffffu, s, off);
            if (L == 0) out[blockIdx.x*BT + b] = sigapx(s + bias);
        }
    }
}

// ---------------- launch ----------------------------------------------------
extern "C" void kernel_launch(void* const* d_in, const int* in_sizes, int n_in,
                              void* d_out, int out_size)
{
    const float* x    = (const float*)d_in[0];
    const float* Wih0 = (const float*)d_in[1];
    const float* Whh0 = (const float*)d_in[2];
    const float* bih0 = (const float*)d_in[3];
    const float* bhh0 = (const float*)d_in[4];
    const float* Wih1 = (const float*)d_in[5];
    const float* Whh1 = (const float*)d_in[6];
    const float* bih1 = (const float*)d_in[7];
    const float* bhh1 = (const float*)d_in[8];
    const float* Wfc  = (const float*)d_in[9];
    const float* bfc  = (const float*)d_in[10];

    cudaFuncSetAttribute(lstm_mma_kernel,
                         cudaFuncAttributeMaxDynamicSharedMemorySize, SMEM_BYTES);

    setup_kernel<<<4096, 256>>>(x, Whh0, Wih1, Whh1, bih0, bhh0, bih1, bhh1);
    lstm_mma_kernel<<<NCTA, NTHR, SMEM_BYTES>>>(Wih0, Wfc, bfc, (float*)d_out);
}